// round 11
// baseline (speedup 1.0000x reference)
#include <cuda_runtime.h>
#include <cuda_bf16.h>
#include <cstdint>

// ============================================================================
// SSIM loss via warp-level bf16 MMA (mma.sync m16n8k16), split weights
// W = W_hi + W_lo (fp32-grade weight precision). One block per (tile,channel):
// grid = 2048*3, no channel loop, only 2 barriers in the hot path.
// ============================================================================

static constexpr int THREADS = 256;
static constexpr int NBLK    = 2048 * 3;
static constexpr float C1c = 1.0e-4f;
static constexpr float C2c = 9.0e-4f;

// dynamic smem offsets (base 1024-aligned)
static constexpr int OFF_A  = 0;        // 256 rows x 128B = 32768 (A1 / C1)
static constexpr int OFF_WH = 32768;    //  64 rows x 128B =  8192
static constexpr int OFF_WL = 40960;    //  64 rows x 128B =  8192
static constexpr int SMEM_BYTES = 49152;

__device__ const float Gk[11] = {
    0.00102840f, 0.00759878f, 0.03600077f, 0.10936042f, 0.21300560f,
    0.26601170f,
    0.21300560f, 0.10936042f, 0.03600077f, 0.00759878f, 0.00102840f
};

__device__ float        g_part[NBLK];
__device__ unsigned int g_count = 0;

// ---------------- helpers ----------------
__device__ __forceinline__ uint32_t smem_u32(const void* p) {
    uint32_t a;
    asm("{ .reg .u64 t; cvta.to.shared.u64 t, %1; cvt.u32.u64 %0, t; }"
        : "=r"(a) : "l"(p));
    return a;
}
__device__ __forceinline__ uint32_t swz(int row, int colb) {
    return (uint32_t)(row * 128 + (colb ^ ((row & 7) << 4)));
}
__device__ __forceinline__ uint32_t pk_bf(float hi, float lo) {
    uint32_t r;
    asm("cvt.rn.bf16x2.f32 %0, %1, %2;" : "=r"(r) : "f"(hi), "f"(lo));
    return r;
}
__device__ __forceinline__ void sts32(uint32_t addr, uint32_t v) {
    asm volatile("st.shared.b32 [%0], %1;" :: "r"(addr), "r"(v));
}
__device__ __forceinline__ void sts16(uint32_t addr, unsigned short v) {
    asm volatile("st.shared.b16 [%0], %1;" :: "r"(addr), "h"(v));
}
__device__ __forceinline__ void ldm_x4(uint32_t* r, uint32_t a) {
    asm volatile("ldmatrix.sync.aligned.m8n8.x4.shared.b16 {%0,%1,%2,%3}, [%4];"
                 : "=r"(r[0]), "=r"(r[1]), "=r"(r[2]), "=r"(r[3]) : "r"(a));
}
__device__ __forceinline__ void ldm_x2(uint32_t* r, uint32_t a) {
    asm volatile("ldmatrix.sync.aligned.m8n8.x2.shared.b16 {%0,%1}, [%2];"
                 : "=r"(r[0]), "=r"(r[1]) : "r"(a));
}
__device__ __forceinline__ void ldm_x2t(uint32_t* r, uint32_t a) {
    asm volatile("ldmatrix.sync.aligned.m8n8.x2.trans.shared.b16 {%0,%1}, [%2];"
                 : "=r"(r[0]), "=r"(r[1]) : "r"(a));
}
__device__ __forceinline__ void mma16816(float* c, const uint32_t* a,
                                         const uint32_t* b) {
    asm volatile(
        "mma.sync.aligned.m16n8k16.row.col.f32.bf16.bf16.f32 "
        "{%0,%1,%2,%3}, {%4,%5,%6,%7}, {%8,%9}, {%0,%1,%2,%3};"
        : "+f"(c[0]), "+f"(c[1]), "+f"(c[2]), "+f"(c[3])
        : "r"(a[0]), "r"(a[1]), "r"(a[2]), "r"(a[3]), "r"(b[0]), "r"(b[1]));
}

__global__ __launch_bounds__(THREADS, 3)
void ssim_main(const float* __restrict__ pred, const float* __restrict__ gt,
               float* __restrict__ out)
{
    extern __shared__ __align__(1024) uint8_t dyn[];
    __shared__ float red[THREADS / 32];
    __shared__ unsigned int ticket;

    const uint32_t SB  = smem_u32(dyn);
    const uint32_t AB  = SB + OFF_A;
    const uint32_t WB  = SB + OFF_WH;
    const uint32_t WLB = SB + OFF_WL;

    const int tid  = threadIdx.x;
    const int warp = tid >> 5;
    const int lane = tid & 31;
    const int g    = lane >> 2;
    const int tig  = lane & 3;

    const int tile = blockIdx.x / 3;
    const int ch   = blockIdx.x - tile * 3;
    const float* pb = pred + (size_t)tile * 12288;
    const float* gb = gt   + (size_t)tile * 12288;

    // ---- phase 0 (no barrier inside): build W split AND A1 concurrently ----
    // W[n][k] = G[k-n], rows n>=54 zero
    for (int i = tid; i < 4096; i += THREADS) {
        const int n = i >> 6, k = i & 63, d = k - n;
        float w = 0.0f;
        if (n < 54 && d >= 0 && d < 11) w = Gk[d];
        const __nv_bfloat16 whi = __float2bfloat16(w);
        const __nv_bfloat16 wlo = __float2bfloat16(w - __bfloat162float(whi));
        sts16(WB  + swz(n, k * 2), *(const unsigned short*)&whi);
        sts16(WLB + swz(n, k * 2), *(const unsigned short*)&wlo);
    }
    // A1: rows sig*64+r, cols c; signals u=x+y, v=x-y, u^2, v^2 (bf16)
    for (int idx = tid; idx < 2048; idx += THREADS) {
        const int pix = idx * 2;
        const int r = pix >> 6, c = pix & 63;
        const float x0 = pb[pix * 3 + ch],     y0 = gb[pix * 3 + ch];
        const float x1 = pb[pix * 3 + 3 + ch], y1 = gb[pix * 3 + 3 + ch];
        const float u0 = x0 + y0, v0 = x0 - y0;
        const float u1 = x1 + y1, v1 = x1 - y1;
        sts32(AB + swz(r,       c * 2), pk_bf(u1, u0));
        sts32(AB + swz(64 + r,  c * 2), pk_bf(v1, v0));
        sts32(AB + swz(128 + r, c * 2), pk_bf(u1 * u1, u0 * u0));
        sts32(AB + swz(192 + r, c * 2), pk_bf(v1 * v1, v0 * v0));
    }
    __syncthreads();                                     // barrier 1

    float local = 0.0f;

    // ================= GEMM1 (horizontal), m-half at a time ===============
    // band: n-tile j range per k-tile kt; j=7 (n 56..63, all-zero W) pruned
    {
        #pragma unroll
        for (int mi = 0; mi < 2; ++mi) {
            const int m0 = warp * 32 + mi * 16;
            float acc[7][4] = {};
            #pragma unroll
            for (int kt = 0; kt < 4; ++kt) {
                const int JST[4] = {0, 0, 2, 4};
                const int JCN[4] = {2, 4, 4, 3};
                uint32_t af[4];
                {
                    const int row  = m0 + (lane & 15);
                    const int colb = kt * 32 + (lane >> 4) * 16;
                    ldm_x4(af, AB + swz(row, colb));
                }
                uint32_t bh[4][2], bl[4][2];
                #pragma unroll
                for (int jj = 0; jj < 4; ++jj) {
                    if (jj < JCN[kt]) {
                        const int nrow = 8 * (JST[kt] + jj) + (lane & 7);
                        const int colb = kt * 32 + ((lane >> 3) & 1) * 16;
                        ldm_x2(bh[jj], WB  + swz(nrow, colb));
                        ldm_x2(bl[jj], WLB + swz(nrow, colb));
                    }
                }
                #pragma unroll
                for (int jj = 0; jj < 4; ++jj) {
                    if (jj < JCN[kt]) {
                        const int j = JST[kt] + jj;
                        mma16816(acc[j], af, bh[jj]);
                        mma16816(acc[j], af, bl[jj]);
                    }
                }
            }
            // store C1 rows (warp-private; cols 0..55, rest masked later)
            const int r0 = m0 + g;
            #pragma unroll
            for (int j = 0; j < 7; ++j) {
                const int colb = j * 16 + tig * 4;
                sts32(AB + swz(r0,     colb), pk_bf(acc[j][1], acc[j][0]));
                sts32(AB + swz(r0 + 8, colb), pk_bf(acc[j][3], acc[j][2]));
            }
        }
    }
    __syncthreads();                                     // barrier 2

    // ================= GEMM2 (vertical) + epilogue ========================
    {
        const int mh = warp & 1;     // rows 32*mh..
        const int nq = warp >> 1;    // cols 16*nq..

        // W fragments, hoisted: combos (mi, t) -> kt = 2*mh+mi+t
        uint32_t wh[4][4], wl[4][4];
        #pragma unroll
        for (int mi = 0; mi < 2; ++mi) {
            const int mt = 2 * mh + mi;
            #pragma unroll
            for (int t = 0; t < 2; ++t) {
                const int kt = mt + t;
                if (kt < 4) {
                    const int row  = mt * 16 + (lane & 15);
                    const int colb = kt * 32 + (lane >> 4) * 16;
                    ldm_x4(wh[2 * mi + t], WB  + swz(row, colb));
                    ldm_x4(wl[2 * mi + t], WLB + swz(row, colb));
                }
            }
        }

        #pragma unroll
        for (int nn = 0; nn < 2; ++nn) {
            float acc[4][2][4] = {};
            #pragma unroll
            for (int krel = 0; krel < 3; ++krel) {
                const int kt = 2 * mh + krel;
                if (kt < 4) {
                    uint32_t bf[4][2];
                    #pragma unroll
                    for (int s = 0; s < 4; ++s) {
                        const int srow = s * 64 + kt * 16 + (lane & 15);
                        const int colb = (2 * nq + nn) * 16;
                        ldm_x2t(bf[s], AB + swz(srow, colb));
                    }
                    #pragma unroll
                    for (int s = 0; s < 4; ++s) {
                        if (krel <= 1) {     // mi=0 frag index = krel
                            mma16816(acc[s][0], wh[krel], bf[s]);
                            mma16816(acc[s][0], wl[krel], bf[s]);
                        }
                        if (krel >= 1) {     // mi=1 frag index = krel+1
                            mma16816(acc[s][1], wh[krel + 1], bf[s]);
                            mma16816(acc[s][1], wl[krel + 1], bf[s]);
                        }
                    }
                }
            }
            // epilogue for this n-half
            #pragma unroll
            for (int mi = 0; mi < 2; ++mi) {
                const int m0e = 32 * mh + 16 * mi;
                const int n0e = (2 * nq + nn) * 8;
                #pragma unroll
                for (int e = 0; e < 4; ++e) {
                    const int r = m0e + g + ((e >= 2) ? 8 : 0);
                    const int c = n0e + 2 * tig + (e & 1);
                    if (r < 54 && c < 54) {
                        const float p  = acc[0][mi][e];
                        const float q  = acc[1][mi][e];
                        const float su = acc[2][mi][e];
                        const float sv = acc[3][mi][e];
                        const float P = p * p, Q = q * q;
                        const float A = 0.5f * (P - Q);
                        const float B = 0.5f * (P + Q);
                        const float num = (A + C1c) * (fmaf(0.5f, su - sv, C2c) - A);
                        const float den = (B + C1c) * (fmaf(0.5f, su + sv, C2c) - B);
                        local += __fdividef(num, den);
                    }
                }
            }
        }
    }

    // ================= deterministic reduction ============================
    __syncthreads();
    #pragma unroll
    for (int off = 16; off > 0; off >>= 1)
        local += __shfl_down_sync(0xffffffffu, local, off);
    if (lane == 0) red[warp] = local;
    __syncthreads();
    if (tid == 0) {
        float sum = 0.0f;
        #pragma unroll
        for (int w = 0; w < THREADS / 32; ++w) sum += red[w];
        g_part[blockIdx.x] = sum;
        __threadfence();
        ticket = atomicAdd(&g_count, 1u);
    }
    __syncthreads();

    if (ticket == NBLK - 1) {
        float sum = 0.0f;
        for (int i = tid; i < NBLK; i += THREADS) sum += g_part[i];
        #pragma unroll
        for (int off = 16; off > 0; off >>= 1)
            sum += __shfl_down_sync(0xffffffffu, sum, off);
        if (lane == 0) red[warp] = sum;
        __syncthreads();
        if (tid == 0) {
            float t = 0.0f;
            #pragma unroll
            for (int w = 0; w < THREADS / 32; ++w) t += red[w];
            out[0] = 1.0f - t * (1.0f / 17915904.0f);   // 2048*3*54*54
            g_count = 0;                                 // reset for replay
        }
    }
}

extern "C" void kernel_launch(void* const* d_in, const int* in_sizes, int n_in,
                              void* d_out, int out_size)
{
    const float* pred = (const float*)d_in[0];
    const float* gt   = (const float*)d_in[1];
    float* out        = (float*)d_out;

    cudaFuncSetAttribute(ssim_main, cudaFuncAttributeMaxDynamicSharedMemorySize,
                         SMEM_BYTES);
    ssim_main<<<NBLK, THREADS, SMEM_BYTES>>>(pred, gt, out);
}

// round 12
// speedup vs baseline: 1.0398x; 1.0398x over previous
#include <cuda_runtime.h>
#include <cuda_bf16.h>
#include <cstdint>

// ============================================================================
// Hybrid SSIM loss: 3/8 of tiles use the FFMA-imm separable-conv path (fma
// pipe), 5/8 use the warp-MMA split-weight path (tensor pipe). Both engines
// run concurrently on each SM (2 CTAs/SM, types interleaved by blockIdx).
// ============================================================================

static constexpr int THREADS = 384;
static constexpr int NBLK    = 2048;
static constexpr float C1c = 1.0e-4f;
static constexpr float C2c = 9.0e-4f;

__device__ constexpr float Gk[11] = {
    0.00102840f, 0.00759878f, 0.03600077f, 0.10936042f, 0.21300560f,
    0.26601170f,
    0.21300560f, 0.10936042f, 0.03600077f, 0.00759878f, 0.00102840f
};

// ---- dynamic smem: union of the two layouts (49,152 B) ----
// FFMA path: plane u32[64][67] @0 (17152) | hpq u32[64][55] @17152 (14080)
//            | hs u32[64][55] @31232 (14080)
// MMA  path: A/C1 @0 (32768) | W_hi @32768 (8192) | W_lo @40960 (8192)
static constexpr int F_PLANE = 0;
static constexpr int F_HPQ   = 17152;
static constexpr int F_HS    = 31232;
static constexpr int OFF_A   = 0;
static constexpr int OFF_WH  = 32768;
static constexpr int OFF_WL  = 40960;
static constexpr int SMEM_BYTES = 49152;

__device__ float        g_part[NBLK];
__device__ unsigned int g_count = 0;

// ---------------- helpers ----------------
__device__ __forceinline__ uint32_t smem_u32(const void* p) {
    uint32_t a;
    asm("{ .reg .u64 t; cvta.to.shared.u64 t, %1; cvt.u32.u64 %0, t; }"
        : "=r"(a) : "l"(p));
    return a;
}
__device__ __forceinline__ uint32_t swz(int row, int colb) {
    return (uint32_t)(row * 128 + (colb ^ ((row & 7) << 4)));
}
__device__ __forceinline__ uint32_t pk_bf(float hi, float lo) {
    uint32_t r;
    asm("cvt.rn.bf16x2.f32 %0, %1, %2;" : "=r"(r) : "f"(hi), "f"(lo));
    return r;
}
__device__ __forceinline__ float lo_f(uint32_t w) { return __uint_as_float(w << 16); }
__device__ __forceinline__ float hi_f(uint32_t w) { return __uint_as_float(w & 0xFFFF0000u); }
__device__ __forceinline__ void sts32(uint32_t a, uint32_t v) {
    asm volatile("st.shared.b32 [%0], %1;" :: "r"(a), "r"(v));
}
__device__ __forceinline__ void sts16(uint32_t a, unsigned short v) {
    asm volatile("st.shared.b16 [%0], %1;" :: "r"(a), "h"(v));
}
__device__ __forceinline__ uint32_t lds32(uint32_t a) {
    uint32_t v;
    asm volatile("ld.shared.b32 %0, [%1];" : "=r"(v) : "r"(a));
    return v;
}
__device__ __forceinline__ void ldm_x4(uint32_t* r, uint32_t a) {
    asm volatile("ldmatrix.sync.aligned.m8n8.x4.shared.b16 {%0,%1,%2,%3}, [%4];"
                 : "=r"(r[0]), "=r"(r[1]), "=r"(r[2]), "=r"(r[3]) : "r"(a));
}
__device__ __forceinline__ void ldm_x2(uint32_t* r, uint32_t a) {
    asm volatile("ldmatrix.sync.aligned.m8n8.x2.shared.b16 {%0,%1}, [%2];"
                 : "=r"(r[0]), "=r"(r[1]) : "r"(a));
}
__device__ __forceinline__ void ldm_x2t(uint32_t* r, uint32_t a) {
    asm volatile("ldmatrix.sync.aligned.m8n8.x2.trans.shared.b16 {%0,%1}, [%2];"
                 : "=r"(r[0]), "=r"(r[1]) : "r"(a));
}
__device__ __forceinline__ void mma16816(float* c, const uint32_t* a,
                                         const uint32_t* b) {
    asm volatile(
        "mma.sync.aligned.m16n8k16.row.col.f32.bf16.bf16.f32 "
        "{%0,%1,%2,%3}, {%4,%5,%6,%7}, {%8,%9}, {%0,%1,%2,%3};"
        : "+f"(c[0]), "+f"(c[1]), "+f"(c[2]), "+f"(c[3])
        : "r"(a[0]), "r"(a[1]), "r"(a[2]), "r"(a[3]), "r"(b[0]), "r"(b[1]));
}

__global__ __launch_bounds__(THREADS, 2)
void ssim_main(const float* __restrict__ pred, const float* __restrict__ gt,
               float* __restrict__ out)
{
    extern __shared__ __align__(1024) uint8_t dyn[];
    __shared__ float red[THREADS / 32];
    __shared__ unsigned int ticket;

    const uint32_t SB = smem_u32(dyn);
    const int tid  = threadIdx.x;
    const int warp = tid >> 5;
    const int lane = tid & 31;

    const float* pb = pred + (size_t)blockIdx.x * 12288;
    const float* gb = gt   + (size_t)blockIdx.x * 12288;

    float local = 0.0f;

    if ((blockIdx.x & 7) < 3) {
        // ====================================================================
        // PATH F: FFMA-imm separable conv (R5 body, proven)
        // ====================================================================
        for (int ch = 0; ch < 3; ++ch) {
            __syncthreads();
            for (int i = tid; i < 4096; i += THREADS) {
                const float x = pb[i * 3 + ch];
                const float y = gb[i * 3 + ch];
                sts32(SB + F_PLANE + (uint32_t)(((i >> 6) * 67 + (i & 63)) * 4),
                      pk_bf(x - y, x + y));                 // hi=v, lo=u
            }
            __syncthreads();
            {   // horizontal: seg=tid/64 (6 segs x 9 cols), r=tid%64
                const int seg = tid / 64;
                const int r   = tid & 63;
                const int c0  = seg * 9;
                float a0[9] = {}, a1[9] = {}, a2[9] = {}, a3[9] = {};
                #pragma unroll
                for (int j = 0; j < 19; ++j) {
                    const uint32_t w =
                        lds32(SB + F_PLANE + (uint32_t)((r * 67 + c0 + j) * 4));
                    const float u = lo_f(w), v = hi_f(w);
                    const float uu = u * u, vv = v * v;
                    #pragma unroll
                    for (int k = 0; k < 11; ++k) {
                        const int o = j - k;
                        if (o >= 0 && o < 9) {
                            a0[o] = fmaf(u,  Gk[k], a0[o]);
                            a1[o] = fmaf(v,  Gk[k], a1[o]);
                            a2[o] = fmaf(uu, Gk[k], a2[o]);
                            a3[o] = fmaf(vv, Gk[k], a3[o]);
                        }
                    }
                }
                #pragma unroll
                for (int o = 0; o < 9; ++o) {
                    const uint32_t idx = (uint32_t)((r * 55 + c0 + o) * 4);
                    sts32(SB + F_HPQ + idx, pk_bf(a1[o], a0[o]));
                    sts32(SB + F_HS  + idx, pk_bf(a3[o], a2[o]));
                }
            }
            __syncthreads();
            if (tid < 324) {   // vertical + ssim: 6 row-segs x 54 cols
                const int c  = tid % 54;
                const int r0 = (tid / 54) * 9;
                float a0[9] = {}, a1[9] = {}, a2[9] = {}, a3[9] = {};
                #pragma unroll
                for (int j = 0; j < 19; ++j) {
                    const uint32_t idx = (uint32_t)(((r0 + j) * 55 + c) * 4);
                    const uint32_t wpq = lds32(SB + F_HPQ + idx);
                    const uint32_t ws  = lds32(SB + F_HS  + idx);
                    const float p  = lo_f(wpq), q  = hi_f(wpq);
                    const float su = lo_f(ws),  sv = hi_f(ws);
                    #pragma unroll
                    for (int k = 0; k < 11; ++k) {
                        const int o = j - k;
                        if (o >= 0 && o < 9) {
                            a0[o] = fmaf(p,  Gk[k], a0[o]);
                            a1[o] = fmaf(q,  Gk[k], a1[o]);
                            a2[o] = fmaf(su, Gk[k], a2[o]);
                            a3[o] = fmaf(sv, Gk[k], a3[o]);
                        }
                    }
                }
                #pragma unroll
                for (int o = 0; o < 9; ++o) {
                    const float p = a0[o], q = a1[o];
                    const float P = p * p, Q = q * q;
                    const float A = 0.5f * (P - Q);
                    const float B = 0.5f * (P + Q);
                    const float num = (A + C1c) * (fmaf(0.5f, a2[o] - a3[o], C2c) - A);
                    const float den = (B + C1c) * (fmaf(0.5f, a2[o] + a3[o], C2c) - B);
                    local += __fdividef(num, den);
                }
            }
        }
    } else {
        // ====================================================================
        // PATH M: warp-MMA split-weight conv (R10 body; warps 0-7 do GEMMs)
        // ====================================================================
        const uint32_t AB  = SB + OFF_A;
        const uint32_t WB  = SB + OFF_WH;
        const uint32_t WLB = SB + OFF_WL;
        const int g   = lane >> 2;
        const int tig = lane & 3;

        for (int i = tid; i < 4096; i += THREADS) {
            const int n = i >> 6, k = i & 63, d = k - n;
            float w = 0.0f;
            if (n < 54 && d >= 0 && d < 11) w = Gk[d];
            const __nv_bfloat16 whi = __float2bfloat16(w);
            const __nv_bfloat16 wlo = __float2bfloat16(w - __bfloat162float(whi));
            sts16(WB  + swz(n, k * 2), *(const unsigned short*)&whi);
            sts16(WLB + swz(n, k * 2), *(const unsigned short*)&wlo);
        }

        for (int ch = 0; ch < 3; ++ch) {
            __syncthreads();
            for (int idx = tid; idx < 2048; idx += THREADS) {
                const int pix = idx * 2;
                const int r = pix >> 6, c = pix & 63;
                const float x0 = pb[pix * 3 + ch],     y0 = gb[pix * 3 + ch];
                const float x1 = pb[pix * 3 + 3 + ch], y1 = gb[pix * 3 + 3 + ch];
                const float u0 = x0 + y0, v0 = x0 - y0;
                const float u1 = x1 + y1, v1 = x1 - y1;
                sts32(AB + swz(r,       c * 2), pk_bf(u1, u0));
                sts32(AB + swz(64 + r,  c * 2), pk_bf(v1, v0));
                sts32(AB + swz(128 + r, c * 2), pk_bf(u1 * u1, u0 * u0));
                sts32(AB + swz(192 + r, c * 2), pk_bf(v1 * v1, v0 * v0));
            }
            __syncthreads();

            if (warp < 8) {   // GEMM1 (horizontal), m-half at a time
                #pragma unroll
                for (int mi = 0; mi < 2; ++mi) {
                    const int m0 = warp * 32 + mi * 16;
                    float acc[7][4] = {};
                    #pragma unroll
                    for (int kt = 0; kt < 4; ++kt) {
                        const int JST[4] = {0, 0, 2, 4};
                        const int JCN[4] = {2, 4, 4, 3};
                        uint32_t af[4];
                        ldm_x4(af, AB + swz(m0 + (lane & 15),
                                            kt * 32 + (lane >> 4) * 16));
                        uint32_t bh[4][2], bl[4][2];
                        #pragma unroll
                        for (int jj = 0; jj < 4; ++jj) {
                            if (jj < JCN[kt]) {
                                const int nrow = 8 * (JST[kt] + jj) + (lane & 7);
                                const int colb = kt * 32 + ((lane >> 3) & 1) * 16;
                                ldm_x2(bh[jj], WB  + swz(nrow, colb));
                                ldm_x2(bl[jj], WLB + swz(nrow, colb));
                            }
                        }
                        #pragma unroll
                        for (int jj = 0; jj < 4; ++jj) {
                            if (jj < JCN[kt]) {
                                const int j = JST[kt] + jj;
                                mma16816(acc[j], af, bh[jj]);
                                mma16816(acc[j], af, bl[jj]);
                            }
                        }
                    }
                    const int r0 = m0 + g;
                    #pragma unroll
                    for (int j = 0; j < 7; ++j) {
                        const int colb = j * 16 + tig * 4;
                        sts32(AB + swz(r0,     colb), pk_bf(acc[j][1], acc[j][0]));
                        sts32(AB + swz(r0 + 8, colb), pk_bf(acc[j][3], acc[j][2]));
                    }
                }
            }
            __syncthreads();

            if (warp < 8) {   // GEMM2 (vertical) + epilogue
                const int mh = warp & 1;
                const int nq = warp >> 1;
                uint32_t wh[4][4], wl[4][4];
                #pragma unroll
                for (int mi = 0; mi < 2; ++mi) {
                    const int mt = 2 * mh + mi;
                    #pragma unroll
                    for (int t = 0; t < 2; ++t) {
                        const int kt = mt + t;
                        if (kt < 4) {
                            const int row  = mt * 16 + (lane & 15);
                            const int colb = kt * 32 + (lane >> 4) * 16;
                            ldm_x4(wh[2 * mi + t], WB  + swz(row, colb));
                            ldm_x4(wl[2 * mi + t], WLB + swz(row, colb));
                        }
                    }
                }
                #pragma unroll
                for (int nn = 0; nn < 2; ++nn) {
                    float acc[4][2][4] = {};
                    #pragma unroll
                    for (int krel = 0; krel < 3; ++krel) {
                        const int kt = 2 * mh + krel;
                        if (kt < 4) {
                            uint32_t bf[4][2];
                            #pragma unroll
                            for (int s = 0; s < 4; ++s)
                                ldm_x2t(bf[s], AB + swz(s * 64 + kt * 16 + (lane & 15),
                                                        (2 * nq + nn) * 16));
                            #pragma unroll
                            for (int s = 0; s < 4; ++s) {
                                if (krel <= 1) {
                                    mma16816(acc[s][0], wh[krel], bf[s]);
                                    mma16816(acc[s][0], wl[krel], bf[s]);
                                }
                                if (krel >= 1) {
                                    mma16816(acc[s][1], wh[krel + 1], bf[s]);
                                    mma16816(acc[s][1], wl[krel + 1], bf[s]);
                                }
                            }
                        }
                    }
                    #pragma unroll
                    for (int mi = 0; mi < 2; ++mi) {
                        const int m0e = 32 * mh + 16 * mi;
                        const int n0e = (2 * nq + nn) * 8;
                        #pragma unroll
                        for (int e = 0; e < 4; ++e) {
                            const int r = m0e + g + ((e >= 2) ? 8 : 0);
                            const int c = n0e + 2 * tig + (e & 1);
                            if (r < 54 && c < 54) {
                                const float p  = acc[0][mi][e];
                                const float q  = acc[1][mi][e];
                                const float su = acc[2][mi][e];
                                const float sv = acc[3][mi][e];
                                const float P = p * p, Q = q * q;
                                const float A = 0.5f * (P - Q);
                                const float B = 0.5f * (P + Q);
                                const float num = (A + C1c) * (fmaf(0.5f, su - sv, C2c) - A);
                                const float den = (B + C1c) * (fmaf(0.5f, su + sv, C2c) - B);
                                local += __fdividef(num, den);
                            }
                        }
                    }
                }
            }
        }
    }

    // ================= deterministic reduction ============================
    __syncthreads();
    #pragma unroll
    for (int off = 16; off > 0; off >>= 1)
        local += __shfl_down_sync(0xffffffffu, local, off);
    if (lane == 0) red[warp] = local;
    __syncthreads();
    if (tid == 0) {
        float sum = 0.0f;
        #pragma unroll
        for (int w = 0; w < THREADS / 32; ++w) sum += red[w];
        g_part[blockIdx.x] = sum;
        __threadfence();
        ticket = atomicAdd(&g_count, 1u);
    }
    __syncthreads();

    if (ticket == NBLK - 1) {
        float sum = 0.0f;
        for (int i = tid; i < NBLK; i += THREADS) sum += g_part[i];
        #pragma unroll
        for (int off = 16; off > 0; off >>= 1)
            sum += __shfl_down_sync(0xffffffffu, sum, off);
        if (lane == 0) red[warp] = sum;
        __syncthreads();
        if (tid == 0) {
            float t = 0.0f;
            #pragma unroll
            for (int w = 0; w < THREADS / 32; ++w) t += red[w];
            out[0] = 1.0f - t * (1.0f / 17915904.0f);   // 2048*3*54*54
            g_count = 0;                                 // reset for replay
        }
    }
}

extern "C" void kernel_launch(void* const* d_in, const int* in_sizes, int n_in,
                              void* d_out, int out_size)
{
    const float* pred = (const float*)d_in[0];
    const float* gt   = (const float*)d_in[1];
    float* out        = (float*)d_out;

    cudaFuncSetAttribute(ssim_main, cudaFuncAttributeMaxDynamicSharedMemorySize,
                         SMEM_BYTES);
    ssim_main<<<NBLK, THREADS, SMEM_BYTES>>>(pred, gt, out);
}

// round 13
// speedup vs baseline: 1.2759x; 1.2270x over previous
#include <cuda_runtime.h>
#include <cuda_bf16.h>
#include <cstdint>

// ============================================================================
// SSIM loss, separable Gaussian, 4-signal (u=x+y, v=x-y), bf16-staged smem,
// FFMA-imm convolution. R13: single fully-coalesced float4 gmem pass builds
// all 3 channel planes; intermediates paired as u64 (LDS.64/STS.64).
// ============================================================================

static constexpr int THREADS = 384;
static constexpr int NBLK    = 2048;
static constexpr float C1 = 1.0e-4f;
static constexpr float C2 = 9.0e-4f;

__device__ constexpr float G[11] = {
    0.00102840f, 0.00759878f, 0.03600077f, 0.10936042f, 0.21300560f,
    0.26601170f,
    0.21300560f, 0.10936042f, 0.03600077f, 0.00759878f, 0.00102840f
};

// dynamic smem layout
//   plane[3][64][67] u32  @ 0       : 51,456 B   bf16x2 (hi=v, lo=u)
//   hb[64][55] u64        @ 51456   : 28,160 B   lo=hpq word, hi=hs word
static constexpr int OFF_PL = 0;
static constexpr int OFF_HB = 51456;
static constexpr int SMEM_BYTES = 79616;
static constexpr int PL_CH = 64 * 67;   // u32 words per channel plane

__device__ float        g_part[NBLK];
__device__ unsigned int g_count = 0;

__device__ __forceinline__ uint32_t smem_u32(const void* p) {
    uint32_t a;
    asm("{ .reg .u64 t; cvta.to.shared.u64 t, %1; cvt.u32.u64 %0, t; }"
        : "=r"(a) : "l"(p));
    return a;
}
__device__ __forceinline__ uint32_t pk(float hi, float lo) {
    uint32_t r;
    asm("cvt.rn.bf16x2.f32 %0, %1, %2;" : "=r"(r) : "f"(hi), "f"(lo));
    return r;
}
__device__ __forceinline__ float lo_f(uint32_t w) { return __uint_as_float(w << 16); }
__device__ __forceinline__ float hi_f(uint32_t w) { return __uint_as_float(w & 0xFFFF0000u); }
__device__ __forceinline__ void sts32(uint32_t a, uint32_t v) {
    asm volatile("st.shared.b32 [%0], %1;" :: "r"(a), "r"(v));
}
__device__ __forceinline__ void sts64(uint32_t a, uint32_t lo, uint32_t hi) {
    asm volatile("{ .reg .b64 t; mov.b64 t, {%1, %2}; st.shared.b64 [%0], t; }"
                 :: "r"(a), "r"(lo), "r"(hi));
}
__device__ __forceinline__ uint32_t lds32(uint32_t a) {
    uint32_t v;
    asm volatile("ld.shared.b32 %0, [%1];" : "=r"(v) : "r"(a));
    return v;
}
__device__ __forceinline__ void lds64(uint32_t a, uint32_t& lo, uint32_t& hi) {
    asm volatile("{ .reg .b64 t; ld.shared.b64 t, [%2]; mov.b64 {%0, %1}, t; }"
                 : "=r"(lo), "=r"(hi) : "r"(a));
}

__global__ __launch_bounds__(THREADS, 2)
void ssim_main(const float* __restrict__ pred, const float* __restrict__ gt,
               float* __restrict__ out)
{
    extern __shared__ __align__(16) uint8_t dyn[];
    __shared__ float red[THREADS / 32];
    __shared__ unsigned int ticket;

    const uint32_t SB = smem_u32(dyn);
    const uint32_t PL = SB + OFF_PL;
    const uint32_t HB = SB + OFF_HB;

    const int tid  = threadIdx.x;
    const int warp = tid >> 5;
    const int lane = tid & 31;

    const float4* pf = (const float4*)(pred + (size_t)blockIdx.x * 12288);
    const float4* gf = (const float4*)(gt   + (size_t)blockIdx.x * 12288);

    // ---- single coalesced load pass: all 3 channel planes -----------------
    for (int j = tid; j < 3072; j += THREADS) {     // 8 iters, LDG.128
        const float4 xv = pf[j];
        const float4 yv = gf[j];
        const int base = j * 4;
        const float xs[4] = {xv.x, xv.y, xv.z, xv.w};
        const float ys[4] = {yv.x, yv.y, yv.z, yv.w};
        #pragma unroll
        for (int e = 0; e < 4; ++e) {
            const int idx = base + e;
            const int pix = idx / 3;                // mul-shift
            const int ch  = idx - pix * 3;
            const int r   = pix >> 6, c = pix & 63;
            const float x = xs[e], y = ys[e];
            sts32(PL + (uint32_t)((ch * PL_CH + r * 67 + c) * 4),
                  pk(x - y, x + y));                // hi=v, lo=u
        }
    }
    __syncthreads();

    float local = 0.0f;

    for (int ch = 0; ch < 3; ++ch) {
        const uint32_t PC = PL + (uint32_t)(ch * PL_CH * 4);

        // ---- horizontal pass: seg=tid/64 (6 segs x 9 cols), r=tid%64 ------
        {
            const int seg = tid / 64;
            const int r   = tid & 63;
            const int c0  = seg * 9;
            const uint32_t rowa = PC + (uint32_t)((r * 67 + c0) * 4);

            float a0[9] = {}, a1[9] = {}, a2[9] = {}, a3[9] = {};
            #pragma unroll
            for (int j = 0; j < 19; ++j) {
                const uint32_t w = lds32(rowa + (uint32_t)(j * 4));
                const float u = lo_f(w), v = hi_f(w);
                const float uu = u * u, vv = v * v;
                #pragma unroll
                for (int k = 0; k < 11; ++k) {
                    const int o = j - k;                 // compile-time pruned
                    if (o >= 0 && o < 9) {
                        a0[o] = fmaf(u,  G[k], a0[o]);   // FFMA-imm
                        a1[o] = fmaf(v,  G[k], a1[o]);
                        a2[o] = fmaf(uu, G[k], a2[o]);
                        a3[o] = fmaf(vv, G[k], a3[o]);
                    }
                }
            }
            const uint32_t oba = HB + (uint32_t)((r * 55 + c0) * 8);
            #pragma unroll
            for (int o = 0; o < 9; ++o)
                sts64(oba + (uint32_t)(o * 8),
                      pk(a1[o], a0[o]),                  // lo word: (q,p)
                      pk(a3[o], a2[o]));                 // hi word: (sv,su)
        }
        __syncthreads();

        // ---- vertical pass + ssim: 324 tasks = 6 row-segs x 54 cols -------
        if (tid < 324) {
            const int c  = tid % 54;
            const int r0 = (tid / 54) * 9;
            const uint32_t cba = HB + (uint32_t)((r0 * 55 + c) * 8);

            float a0[9] = {}, a1[9] = {}, a2[9] = {}, a3[9] = {};
            #pragma unroll
            for (int j = 0; j < 19; ++j) {
                uint32_t wpq, ws;
                lds64(cba + (uint32_t)(j * 55 * 8), wpq, ws);
                const float p  = lo_f(wpq), q  = hi_f(wpq);
                const float su = lo_f(ws),  sv = hi_f(ws);
                #pragma unroll
                for (int k = 0; k < 11; ++k) {
                    const int o = j - k;
                    if (o >= 0 && o < 9) {
                        a0[o] = fmaf(p,  G[k], a0[o]);
                        a1[o] = fmaf(q,  G[k], a1[o]);
                        a2[o] = fmaf(su, G[k], a2[o]);
                        a3[o] = fmaf(sv, G[k], a3[o]);
                    }
                }
            }
            #pragma unroll
            for (int o = 0; o < 9; ++o) {
                const float p = a0[o], q = a1[o];
                const float P = p * p, Q = q * q;
                const float A = 0.5f * (P - Q);          // 2*mu1*mu2
                const float B = 0.5f * (P + Q);          // mu1^2 + mu2^2
                const float num = (A + C1) * (fmaf(0.5f, a2[o] - a3[o], C2) - A);
                const float den = (B + C1) * (fmaf(0.5f, a2[o] + a3[o], C2) - B);
                local += __fdividef(num, den);
            }
        }
        if (ch < 2) __syncthreads();   // hb rewritten next channel
    }

    // ---- deterministic reduction ------------------------------------------
    __syncthreads();
    #pragma unroll
    for (int off = 16; off > 0; off >>= 1)
        local += __shfl_down_sync(0xffffffffu, local, off);
    if (lane == 0) red[warp] = local;
    __syncthreads();
    if (tid == 0) {
        float sum = 0.0f;
        #pragma unroll
        for (int w = 0; w < THREADS / 32; ++w) sum += red[w];
        g_part[blockIdx.x] = sum;
        __threadfence();
        ticket = atomicAdd(&g_count, 1u);
    }
    __syncthreads();

    if (ticket == NBLK - 1) {
        float sum = 0.0f;
        for (int i = tid; i < NBLK; i += THREADS) sum += g_part[i];
        #pragma unroll
        for (int off = 16; off > 0; off >>= 1)
            sum += __shfl_down_sync(0xffffffffu, sum, off);
        if (lane == 0) red[warp] = sum;
        __syncthreads();
        if (tid == 0) {
            float t = 0.0f;
            #pragma unroll
            for (int w = 0; w < THREADS / 32; ++w) t += red[w];
            out[0] = 1.0f - t * (1.0f / 17915904.0f);   // 2048*3*54*54
            g_count = 0;                                 // reset for replay
        }
    }
}

extern "C" void kernel_launch(void* const* d_in, const int* in_sizes, int n_in,
                              void* d_out, int out_size)
{
    const float* pred = (const float*)d_in[0];
    const float* gt   = (const float*)d_in[1];
    float* out        = (float*)d_out;

    cudaFuncSetAttribute(ssim_main, cudaFuncAttributeMaxDynamicSharedMemorySize,
                         SMEM_BYTES);
    ssim_main<<<NBLK, THREADS, SMEM_BYTES>>>(pred, gt, out);
}